// round 10
// baseline (speedup 1.0000x reference)
#include <cuda_runtime.h>
#include <cuda_fp16.h>
#include <cstdint>

#define BATCH 4096

// ---------------- device-global staging (written by pre-kernel) ----------------
// gWfrag: fp16 B fragments in direct mma.m16n8k16 per-lane register order.
//   index = ((((chunk*2 + nhalf)*2 + p)*8 + kblk)*32 + lane), one uint4 each:
//     {b0_s0, b1_s0, b0_s1, b1_s1} for the two n8-tiles s of pair p.
//   lane l: in-tile col c = l>>2, k-pair = (l&3)*2:
//     b0_s = W[K..K+1][n(s,c)],  b1_s = W[K+8..K+9][n(s,c)],  K = kblk*16+(l&3)*2
//   col permutation (contiguous epilogue stores):
//     n = chunk*64 + nhalf*32 + 8*(c>>1) + (p*2+s)*2 + (c&1)
__device__ __align__(1024) uint4 gWfrag[8192];
// gT[half][f][h] = sum_c Wlin[f][c] * Watt[(half*512 + c)*8 + h]
__device__ __align__(16) float gT[2][128][8];

// ---------------- PTX helpers ----------------
__device__ __forceinline__ uint32_t smem_u32(const void* p) {
    uint32_t a;
    asm("{ .reg .u64 t; cvta.to.shared.u64 t, %1; cvt.u32.u64 %0, t; }" : "=r"(a) : "l"(p));
    return a;
}
__device__ __forceinline__ void cp_async16(uint32_t saddr, const void* g) {
    asm volatile("cp.async.cg.shared.global [%0], [%1], 16;" :: "r"(saddr), "l"(g));
}
__device__ __forceinline__ void cp_commit() { asm volatile("cp.async.commit_group;"); }
template<int N> __device__ __forceinline__ void cp_wait() {
    asm volatile("cp.async.wait_group %0;" :: "n"(N));
}

#define LDSM_X4(d, a)                                                             \
    asm volatile("ldmatrix.sync.aligned.m8n8.x4.shared.b16 {%0,%1,%2,%3}, [%4];"  \
        : "=r"((d)[0]), "=r"((d)[1]), "=r"((d)[2]), "=r"((d)[3]) : "r"(a))

__device__ __forceinline__ void mmaf16(float* c, const uint32_t* a,
                                       uint32_t b0, uint32_t b1) {
    asm volatile("mma.sync.aligned.m16n8k16.row.col.f32.f16.f16.f32 "
        "{%0,%1,%2,%3}, {%4,%5,%6,%7}, {%8,%9}, {%0,%1,%2,%3};"
        : "+f"(c[0]), "+f"(c[1]), "+f"(c[2]), "+f"(c[3])
        : "r"(a[0]), "r"(a[1]), "r"(a[2]), "r"(a[3]), "r"(b0), "r"(b1));
}

__device__ __forceinline__ uint32_t pkh2(float a, float b) {
    __half2 t = __floats2half2_rn(a, b);
    return *reinterpret_cast<uint32_t*>(&t);
}

// ---------------- fused pre-kernel ----------------
// blocks [0,32): B fragment image; blocks [32,96): T = Wlin @ Watt halves
__global__ void k_prep(const float* __restrict__ Wlin, const float* __restrict__ Watt) {
    int blk = blockIdx.x;
    if (blk < 32) {
        int id = blk * 256 + threadIdx.x;          // 0..8191
        int lane = id & 31, kblk = (id >> 5) & 7, p = (id >> 8) & 1;
        int nhalf = (id >> 9) & 1, chunk = id >> 10;
        int c = lane >> 2, kb2 = (lane & 3) * 2;
        int K = kblk * 16 + kb2;
        uint32_t wv[4];
        #pragma unroll
        for (int s = 0; s < 2; ++s) {
            int n = chunk * 64 + nhalf * 32 + 8 * (c >> 1) + (p * 2 + s) * 2 + (c & 1);
            wv[s * 2 + 0] = pkh2(Wlin[(size_t)K * 512 + n],
                                 Wlin[(size_t)(K + 1) * 512 + n]);
            wv[s * 2 + 1] = pkh2(Wlin[(size_t)(K + 8) * 512 + n],
                                 Wlin[(size_t)(K + 9) * 512 + n]);
        }
        gWfrag[id] = make_uint4(wv[0], wv[1], wv[2], wv[3]);
    } else {
        int t = (blk - 32) * 256 + threadIdx.x;     // 0..16383
        int o = t >> 3, sub = t & 7;                 // 2048 outputs, 8 threads each
        int half = o >> 10, f = (o >> 3) & 127, h = o & 7;
        const float* wl = Wlin + (size_t)f * 512;
        const float* wa = Watt + (size_t)half * 512 * 8 + h;
        float acc = 0.f;
        int c0 = sub * 64;
        #pragma unroll 8
        for (int c = c0; c < c0 + 64; ++c)
            acc += wl[c] * wa[(size_t)c * 8];
        #pragma unroll
        for (int off = 4; off > 0; off >>= 1)
            acc += __shfl_xor_sync(0xffffffffu, acc, off);
        if (sub == 0) gT[half][f][h] = acc;
    }
}

// ---------------- main kernel: 256 threads, 1 batch, 3 CTAs/SM, smem 26.7KB ----
// SMEM: A image [mblk4][kblk8][512B] @0 (16KB) ; T copy @16384 (8KB)
//       SS[8] @24576 ; ATT[8][64] @24640  (total 26688)
#define SM_A   0
#define SM_T   16384
#define SM_SS  24576
#define SM_ATT 24640
#define SMEM_BYTES 26688

__global__ void __launch_bounds__(256, 3)
agg_main(const float* __restrict__ x, const int* __restrict__ mask,
         float* __restrict__ out)
{
    extern __shared__ unsigned char sm[];
    const int t = threadIdx.x, w = t >> 5, lane = t & 31;
    const int b = blockIdx.x;
    const uint32_t sb = smem_u32(sm);
    float* attb = (float*)(sm + SM_ATT);
    float* sS   = (float*)(sm + SM_SS);
    const float* sT0 = (float*)(sm + SM_T);
    const float* sT1 = (float*)(sm + SM_T) + 128 * 8;

    // ---- T -> smem (8KB, one-time) ----
    #pragma unroll
    for (int i = 0; i < 2; ++i) {
        int idx = t + i * 256;
        cp_async16(sb + SM_T + idx * 16, (const char*)gT + idx * 16);
    }
    cp_commit();

    // ---- convert x -> fp16 A image, direct from global (coalesced, L2-policy) ----
    const float* xp = x + (size_t)b * 8192;
    #pragma unroll
    for (int i = 0; i < 4; ++i) {
        int e = t + i * 256;                 // 1024 k-octet entries
        float4 v0 = __ldcg((const float4*)(xp + e * 8));
        float4 v1 = __ldcg((const float4*)(xp + e * 8 + 4));
        int r = e >> 4, ko = e & 15;
        int mblk = r >> 4, rr = r & 15, kblk = ko >> 1, kh = ko & 1;
        uint32_t off = (uint32_t)mblk * 4096u + (uint32_t)kblk * 512u
                     + (((uint32_t)rr * 32u + (uint32_t)kh * 16u) ^ ((rr & 4) ? 16u : 0u));
        *(uint4*)(sm + SM_A + off) = make_uint4(pkh2(v0.x, v0.y), pkh2(v0.z, v0.w),
                                                pkh2(v1.x, v1.y), pkh2(v1.z, v1.w));
    }

    // ---- logits: register-resident x slice, thread = (row r, k-quarter q) ----
    const int lr = t >> 2, lq = t & 3;
    float4 xs[8];
    {
        const float* xr = xp + lr * 128 + lq * 4;
        #pragma unroll
        for (int i = 0; i < 8; ++i)
            xs[i] = __ldcg((const float4*)(xr + i * 16));   // k = i*16 + q*4 + 0..3
    }
    cp_wait<0>();
    __syncthreads();      // T visible (A image also written; barrier reused below)

    float dacc[8];
    #pragma unroll
    for (int h = 0; h < 8; ++h) dacc[h] = 0.f;
    #pragma unroll
    for (int i = 0; i < 8; ++i) {
        const float xv[4] = { xs[i].x, xs[i].y, xs[i].z, xs[i].w };
        #pragma unroll
        for (int jj = 0; jj < 4; ++jj) {
            int k = i * 16 + lq * 4 + jj;
            float4 ta = *(const float4*)(sT1 + k * 8);
            float4 tb = *(const float4*)(sT1 + k * 8 + 4);
            dacc[0] += xv[jj] * ta.x; dacc[1] += xv[jj] * ta.y;
            dacc[2] += xv[jj] * ta.z; dacc[3] += xv[jj] * ta.w;
            dacc[4] += xv[jj] * tb.x; dacc[5] += xv[jj] * tb.y;
            dacc[6] += xv[jj] * tb.z; dacc[7] += xv[jj] * tb.w;
        }
    }
    #pragma unroll
    for (int h = 0; h < 8; ++h) {
        dacc[h] += __shfl_xor_sync(0xffffffffu, dacc[h], 1);
        dacc[h] += __shfl_xor_sync(0xffffffffu, dacc[h], 2);
    }
    if (t < 4) {          // src term: row 0 (threads 0..3 hold its slice) vs T0
        float sacc[8];
        #pragma unroll
        for (int h = 0; h < 8; ++h) sacc[h] = 0.f;
        #pragma unroll
        for (int i = 0; i < 8; ++i) {
            const float xv[4] = { xs[i].x, xs[i].y, xs[i].z, xs[i].w };
            #pragma unroll
            for (int jj = 0; jj < 4; ++jj) {
                int k = i * 16 + lq * 4 + jj;
                float4 ta = *(const float4*)(sT0 + k * 8);
                float4 tb = *(const float4*)(sT0 + k * 8 + 4);
                sacc[0] += xv[jj] * ta.x; sacc[1] += xv[jj] * ta.y;
                sacc[2] += xv[jj] * ta.z; sacc[3] += xv[jj] * ta.w;
                sacc[4] += xv[jj] * tb.x; sacc[5] += xv[jj] * tb.y;
                sacc[6] += xv[jj] * tb.z; sacc[7] += xv[jj] * tb.w;
            }
        }
        #pragma unroll
        for (int h = 0; h < 8; ++h) {
            sacc[h] += __shfl_xor_sync(0xFu, sacc[h], 1);
            sacc[h] += __shfl_xor_sync(0xFu, sacc[h], 2);
        }
        if (t == 0) {
            #pragma unroll
            for (int h = 0; h < 8; ++h) sS[h] = sacc[h];
        }
    }
    __syncthreads();      // sS + A image visible

    // ---- hoist A fragments (chunk-invariant): 32 regs ----
    const int mblk = w >> 1, nhalf = w & 1;
    const int ja = lane >> 3, ra = lane & 7;
    const int ml  = (ja & 1) * 8 + ra, kha = ja >> 1;
    const uint32_t arow = (((uint32_t)ml * 32u + (uint32_t)kha * 16u) ^ ((ml & 4) ? 16u : 0u));
    const uint32_t aad0 = sb + SM_A + (uint32_t)mblk * 4096u + arow;
    uint32_t af[8][4];
    #pragma unroll
    for (int kblk = 0; kblk < 8; ++kblk)
        LDSM_X4(af[kblk], aad0 + (uint32_t)kblk * 512u);

    // ---- finalize logits -> attb ----
    if (lq == 0) {
        #pragma unroll
        for (int h = 0; h < 8; ++h) {
            float v = sS[h] + dacc[h];
            v = (v >= 0.f) ? v : 0.2f * v;
            attb[h * 64 + lr] = v;
        }
    }
    __syncthreads();

    // ---- softmax: warp w -> head w ----
    {
        int m0 = mask[b * 64 + lane];
        int m1 = mask[b * 64 + lane + 32];
        float v0 = attb[w * 64 + lane]      + (m0 == 0 ? -1e9f : 0.f);
        float v1 = attb[w * 64 + lane + 32] + (m1 == 0 ? -1e9f : 0.f);
        float mx = fmaxf(v0, v1);
        #pragma unroll
        for (int o = 16; o > 0; o >>= 1) mx = fmaxf(mx, __shfl_xor_sync(0xffffffffu, mx, o));
        float e0 = __expf(v0 - mx), e1 = __expf(v1 - mx);
        float sum = e0 + e1;
        #pragma unroll
        for (int o = 16; o > 0; o >>= 1) sum += __shfl_xor_sync(0xffffffffu, sum, o);
        float inv = 1.f / sum;
        attb[w * 64 + lane]      = e0 * inv;
        attb[w * 64 + lane + 32] = e1 * inv;
    }
    __syncthreads();      // attb final; mainloop below is barrier-free

    // ---- epilogue lane mapping ----
    const int er = lane >> 2, jj = lane & 3;
    const int ns0 = mblk * 16 + er, ns1 = ns0 + 8;
    float* ob0 = out + ((size_t)b * 64 + ns0) * 512 + nhalf * 32 + jj * 8;
    float* ob1 = out + ((size_t)b * 64 + ns1) * 512 + nhalf * 32 + jj * 8;

    // ---- mainloop: 8 chunks (chunk == head), B fragments via __ldg (L1-hot) ----
    const uint4* bp = gWfrag + (size_t)nhalf * 512 + lane;   // + chunk*1024 + p*256 + kblk*32
    for (int c = 0; c < 8; ++c) {
        const uint4* bc = bp + (size_t)c * 1024;
        float acc[16];
        #pragma unroll
        for (int i = 0; i < 16; ++i) acc[i] = 0.f;

        // depth-1 pipelined: prefetch kblk+1's pair while 4 MMAs on kblk
        uint4 b0 = __ldg(bc), b1 = __ldg(bc + 256);
        #pragma unroll
        for (int kblk = 0; kblk < 8; ++kblk) {
            uint4 n0, n1;
            if (kblk < 7) {
                n0 = __ldg(bc + (kblk + 1) * 32);
                n1 = __ldg(bc + 256 + (kblk + 1) * 32);
            }
            mmaf16(acc + 0,  af[kblk], b0.x, b0.y);   // tile 0 (p0,s0)
            mmaf16(acc + 4,  af[kblk], b0.z, b0.w);   // tile 1 (p0,s1)
            mmaf16(acc + 8,  af[kblk], b1.x, b1.y);   // tile 2 (p1,s0)
            mmaf16(acc + 12, af[kblk], b1.z, b1.w);   // tile 3 (p1,s1)
            b0 = n0; b1 = n1;
        }

        // ---- epilogue: scale by aw, relu, 4x STG.128 ----
        float sc0 = attb[c * 64 + ns0];
        float sc1 = attb[c * 64 + ns1];
        float* o0 = ob0 + c * 64;
        float* o1 = ob1 + c * 64;
        float4 v00 = make_float4(fmaxf(acc[0]  * sc0, 0.f), fmaxf(acc[1]  * sc0, 0.f),
                                 fmaxf(acc[4]  * sc0, 0.f), fmaxf(acc[5]  * sc0, 0.f));
        float4 v01 = make_float4(fmaxf(acc[8]  * sc0, 0.f), fmaxf(acc[9]  * sc0, 0.f),
                                 fmaxf(acc[12] * sc0, 0.f), fmaxf(acc[13] * sc0, 0.f));
        float4 v10 = make_float4(fmaxf(acc[2]  * sc1, 0.f), fmaxf(acc[3]  * sc1, 0.f),
                                 fmaxf(acc[6]  * sc1, 0.f), fmaxf(acc[7]  * sc1, 0.f));
        float4 v11 = make_float4(fmaxf(acc[10] * sc1, 0.f), fmaxf(acc[11] * sc1, 0.f),
                                 fmaxf(acc[14] * sc1, 0.f), fmaxf(acc[15] * sc1, 0.f));
        *(float4*)(o0)     = v00;
        *(float4*)(o0 + 4) = v01;
        *(float4*)(o1)     = v10;
        *(float4*)(o1 + 4) = v11;
    }
}

// ---------------- launch ----------------
extern "C" void kernel_launch(void* const* d_in, const int* in_sizes, int n_in,
                              void* d_out, int out_size)
{
    const float* x    = (const float*)d_in[0];
    const float* Wlin = (const float*)d_in[1];
    const float* Watt = (const float*)d_in[2];
    const int*   mk   = (const int*)d_in[3];
    float*       out  = (float*)d_out;

    k_prep<<<96, 256>>>(Wlin, Watt);

    cudaFuncSetAttribute(agg_main, cudaFuncAttributeMaxDynamicSharedMemorySize, SMEM_BYTES);
    agg_main<<<BATCH, 256, SMEM_BYTES>>>(x, mk, out);
}

// round 11
// speedup vs baseline: 1.0067x; 1.0067x over previous
#include <cuda_runtime.h>
#include <cuda_fp16.h>
#include <cstdint>

#define BATCH 4096

// ---------------- device-global staging (written by pre-kernel) ----------------
// gWimg: fp16 B ldmatrix image, [chunk 8][nblk 8][kblk 8][tile 256B]
//   tile = 8 n-slots x 16 k fp16, slot nr at ((nr*32 + kh*16) ^ ((nr&4)?16:0)) + (k&7)*2
//   N-permutation (contiguous epilogue stores):
//     chunk=n>>6, cc=n&63, nhalf=cc>>5, w32=cc&31, j=w32>>3, g=(w32>>1)&3, r=w32&1
//     nblk = nhalf*4 + g ; slot = 2j + r
__device__ __align__(1024) unsigned char gWimg[131072];
// gT[half][f][h] = sum_c Wlin[f][c] * Watt[(half*512 + c)*8 + h]  (L1-resident in-kernel)
__device__ __align__(16) float gT[2][128][8];

// ---------------- PTX helpers ----------------
__device__ __forceinline__ uint32_t smem_u32(const void* p) {
    uint32_t a;
    asm("{ .reg .u64 t; cvta.to.shared.u64 t, %1; cvt.u32.u64 %0, t; }" : "=r"(a) : "l"(p));
    return a;
}
__device__ __forceinline__ void cp_async16(uint32_t saddr, const void* g) {
    asm volatile("cp.async.cg.shared.global [%0], [%1], 16;" :: "r"(saddr), "l"(g));
}
__device__ __forceinline__ void cp_commit() { asm volatile("cp.async.commit_group;"); }
template<int N> __device__ __forceinline__ void cp_wait() {
    asm volatile("cp.async.wait_group %0;" :: "n"(N));
}

#define LDSM_X4(d, a)                                                             \
    asm volatile("ldmatrix.sync.aligned.m8n8.x4.shared.b16 {%0,%1,%2,%3}, [%4];"  \
        : "=r"((d)[0]), "=r"((d)[1]), "=r"((d)[2]), "=r"((d)[3]) : "r"(a))

__device__ __forceinline__ void mmaf16(float* c, const uint32_t* a,
                                       uint32_t b0, uint32_t b1) {
    asm volatile("mma.sync.aligned.m16n8k16.row.col.f32.f16.f16.f32 "
        "{%0,%1,%2,%3}, {%4,%5,%6,%7}, {%8,%9}, {%0,%1,%2,%3};"
        : "+f"(c[0]), "+f"(c[1]), "+f"(c[2]), "+f"(c[3])
        : "r"(a[0]), "r"(a[1]), "r"(a[2]), "r"(a[3]), "r"(b0), "r"(b1));
}

__device__ __forceinline__ uint32_t pkh2(float a, float b) {
    __half2 t = __floats2half2_rn(a, b);
    return *reinterpret_cast<uint32_t*>(&t);
}

// ---------------- fused pre-kernel ----------------
// blocks [0,32): B fp16 image; blocks [32,96): T = Wlin @ Watt halves
__global__ void k_prep(const float* __restrict__ Wlin, const float* __restrict__ Watt) {
    int blk = blockIdx.x;
    if (blk < 32) {
        int t = blk * 256 + threadIdx.x;      // 0..8191
        int n = t & 511, ko = t >> 9;          // ko: 16 k-octs
        float v[8];
        #pragma unroll
        for (int j = 0; j < 8; ++j)
            v[j] = Wlin[(size_t)(ko * 8 + j) * 512 + n];
        int chunk = n >> 6, cc = n & 63, nhalf = cc >> 5, w32 = cc & 31;
        int jj = w32 >> 3, g = (w32 >> 1) & 3, r = w32 & 1;
        int nblk = chunk * 8 + nhalf * 4 + g;
        int nr = jj * 2 + r;
        int kblk = ko >> 1, kh = ko & 1;
        uint32_t off = (uint32_t)nblk * 2048u + (uint32_t)kblk * 256u
                     + (((uint32_t)nr * 32u + (uint32_t)kh * 16u) ^ ((nr & 4) ? 16u : 0u));
        *(uint4*)(&gWimg[off]) = make_uint4(pkh2(v[0], v[1]), pkh2(v[2], v[3]),
                                            pkh2(v[4], v[5]), pkh2(v[6], v[7]));
    } else {
        int t = (blk - 32) * 256 + threadIdx.x;   // 0..16383
        int o = t >> 3, sub = t & 7;               // 2048 outputs, 8 threads each
        int half = o >> 10, f = (o >> 3) & 127, h = o & 7;
        const float* wl = Wlin + (size_t)f * 512;
        const float* wa = Watt + (size_t)half * 512 * 8 + h;
        float acc = 0.f;
        int c0 = sub * 64;
        #pragma unroll 8
        for (int c = c0; c < c0 + 64; ++c)
            acc += wl[c] * wa[(size_t)c * 8];
        #pragma unroll
        for (int off = 4; off > 0; off >>= 1)
            acc += __shfl_xor_sync(0xffffffffu, acc, off);
        if (sub == 0) gT[half][f][h] = acc;
    }
}

// ---------------- main kernel: 256 threads, 1 batch, 3 CTAs/SM ----------------
// SMEM (bytes): A image [mblk4][kblk8][512B] @0 (16KB)
//               B ring 3 x 16KB @16384 (no aliasing; free from cycle 0)
//               SS[8] @65536 ; ATT[8][64] @65600  (total 67648, proven 3 CTAs/SM)
#define SM_A     0
#define SM_B     16384
#define SM_SS    65536
#define SM_ATT   65600
#define SMEM_BYTES 67648

__global__ void __launch_bounds__(256, 3)
agg_main(const float* __restrict__ x, const int* __restrict__ mask,
         float* __restrict__ out)
{
    extern __shared__ unsigned char sm[];
    const int t = threadIdx.x, w = t >> 5, lane = t & 31;
    const int b = blockIdx.x;
    const uint32_t sb = smem_u32(sm);
    float* attb = (float*)(sm + SM_ATT);
    float* sS   = (float*)(sm + SM_SS);
    const float* gT0 = &gT[0][0][0];
    const float* gT1 = &gT[1][0][0];

    // ---- G0: chunk0 -> buf2 ; G1: chunk1 -> buf0 (ring is free from start) ----
    #pragma unroll
    for (int i = 0; i < 4; ++i) {
        int u = t + i * 256;
        cp_async16(sb + SM_B + 32768u + u * 16, &gWimg[u * 16]);
    }
    cp_commit();
    #pragma unroll
    for (int i = 0; i < 4; ++i) {
        int u = t + i * 256;
        cp_async16(sb + SM_B + u * 16, &gWimg[16384 + u * 16]);
    }
    cp_commit();

    // ---- convert x -> fp16 A image, straight from global (coalesced, L2 policy) ----
    const float* xp = x + (size_t)b * 8192;
    #pragma unroll
    for (int i = 0; i < 4; ++i) {
        int e = t + i * 256;                 // 1024 k-octet entries
        float4 v0 = __ldcg((const float4*)(xp + e * 8));
        float4 v1 = __ldcg((const float4*)(xp + e * 8 + 4));
        int r = e >> 4, ko = e & 15;
        int mblk = r >> 4, rr = r & 15, kblk = ko >> 1, kh = ko & 1;
        uint32_t off = (uint32_t)mblk * 4096u + (uint32_t)kblk * 512u
                     + (((uint32_t)rr * 32u + (uint32_t)kh * 16u) ^ ((rr & 4) ? 16u : 0u));
        *(uint4*)(sm + SM_A + off) = make_uint4(pkh2(v0.x, v0.y), pkh2(v0.z, v0.w),
                                                pkh2(v1.x, v1.y), pkh2(v1.z, v1.w));
    }

    // ---- logits: register-resident x slice, thread = (row lr, k-quarter lq) ----
    const int lr = t >> 2, lq = t & 3;
    float4 xs[8];
    {
        const float* xr = xp + lr * 128 + lq * 4;
        #pragma unroll
        for (int i = 0; i < 8; ++i)
            xs[i] = __ldcg((const float4*)(xr + i * 16));   // k = i*16 + lq*4 + 0..3
    }
    float dacc[8];
    #pragma unroll
    for (int h = 0; h < 8; ++h) dacc[h] = 0.f;
    #pragma unroll
    for (int i = 0; i < 8; ++i) {
        const float xv[4] = { xs[i].x, xs[i].y, xs[i].z, xs[i].w };
        #pragma unroll
        for (int jj = 0; jj < 4; ++jj) {
            int k = i * 16 + lq * 4 + jj;
            float4 ta = __ldg((const float4*)(gT1 + k * 8));
            float4 tb = __ldg((const float4*)(gT1 + k * 8 + 4));
            dacc[0] += xv[jj] * ta.x; dacc[1] += xv[jj] * ta.y;
            dacc[2] += xv[jj] * ta.z; dacc[3] += xv[jj] * ta.w;
            dacc[4] += xv[jj] * tb.x; dacc[5] += xv[jj] * tb.y;
            dacc[6] += xv[jj] * tb.z; dacc[7] += xv[jj] * tb.w;
        }
    }
    #pragma unroll
    for (int h = 0; h < 8; ++h) {
        dacc[h] += __shfl_xor_sync(0xffffffffu, dacc[h], 1);
        dacc[h] += __shfl_xor_sync(0xffffffffu, dacc[h], 2);
    }
    if (t < 4) {          // src term: row 0 slice lives in threads 0..3
        float sacc[8];
        #pragma unroll
        for (int h = 0; h < 8; ++h) sacc[h] = 0.f;
        #pragma unroll
        for (int i = 0; i < 8; ++i) {
            const float xv[4] = { xs[i].x, xs[i].y, xs[i].z, xs[i].w };
            #pragma unroll
            for (int jj = 0; jj < 4; ++jj) {
                int k = i * 16 + lq * 4 + jj;
                float4 ta = __ldg((const float4*)(gT0 + k * 8));
                float4 tb = __ldg((const float4*)(gT0 + k * 8 + 4));
                sacc[0] += xv[jj] * ta.x; sacc[1] += xv[jj] * ta.y;
                sacc[2] += xv[jj] * ta.z; sacc[3] += xv[jj] * ta.w;
                sacc[4] += xv[jj] * tb.x; sacc[5] += xv[jj] * tb.y;
                sacc[6] += xv[jj] * tb.z; sacc[7] += xv[jj] * tb.w;
            }
        }
        #pragma unroll
        for (int h = 0; h < 8; ++h) {
            sacc[h] += __shfl_xor_sync(0xFu, sacc[h], 1);
            sacc[h] += __shfl_xor_sync(0xFu, sacc[h], 2);
        }
        if (t == 0) {
            #pragma unroll
            for (int h = 0; h < 8; ++h) sS[h] = sacc[h];
        }
    }
    __syncthreads();      // A image + sS visible

    // ---- hoist A fragments (chunk-invariant): 32 regs ----
    const int mblk = w >> 1, nhalf = w & 1;
    const int ja = lane >> 3, ra = lane & 7;
    const int ml  = (ja & 1) * 8 + ra, kha = ja >> 1;
    const uint32_t arow = (((uint32_t)ml * 32u + (uint32_t)kha * 16u) ^ ((ml & 4) ? 16u : 0u));
    const uint32_t aad0 = sb + SM_A + (uint32_t)mblk * 4096u + arow;
    uint32_t af[8][4];
    #pragma unroll
    for (int kblk = 0; kblk < 8; ++kblk)
        LDSM_X4(af[kblk], aad0 + (uint32_t)kblk * 512u);

    // ---- finalize logits -> attb ----
    if (lq == 0) {
        #pragma unroll
        for (int h = 0; h < 8; ++h) {
            float v = sS[h] + dacc[h];
            v = (v >= 0.f) ? v : 0.2f * v;
            attb[h * 64 + lr] = v;
        }
    }
    __syncthreads();

    // ---- softmax: warp w -> head w ----
    {
        int m0 = mask[b * 64 + lane];
        int m1 = mask[b * 64 + lane + 32];
        float v0 = attb[w * 64 + lane]      + (m0 == 0 ? -1e9f : 0.f);
        float v1 = attb[w * 64 + lane + 32] + (m1 == 0 ? -1e9f : 0.f);
        float mx = fmaxf(v0, v1);
        #pragma unroll
        for (int o = 16; o > 0; o >>= 1) mx = fmaxf(mx, __shfl_xor_sync(0xffffffffu, mx, o));
        float e0 = __expf(v0 - mx), e1 = __expf(v1 - mx);
        float sum = e0 + e1;
        #pragma unroll
        for (int o = 16; o > 0; o >>= 1) sum += __shfl_xor_sync(0xffffffffu, sum, o);
        float inv = 1.f / sum;
        attb[w * 64 + lane]      = e0 * inv;
        attb[w * 64 + lane + 32] = e1 * inv;
    }

    // ---- B addressing + epilogue lane mapping (permuted columns) ----
    const int nbo = (ja >> 1), khb = ja & 1;
    const uint32_t brow = (((uint32_t)ra * 32u + (uint32_t)khb * 16u) ^ ((ra & 4) ? 16u : 0u));
    const int er = lane >> 2, jc = lane & 3;
    const int ns0 = mblk * 16 + er, ns1 = ns0 + 8;
    float* ob0 = out + ((size_t)b * 64 + ns0) * 512 + nhalf * 32 + jc * 8;
    float* ob1 = out + ((size_t)b * 64 + ns1) * 512 + nhalf * 32 + jc * 8;

    // ---- mainloop: 8 chunks (chunk == head), 3-stage B ring, 1 sync/chunk ----
    // chunk m in buf (m+2)%3; iter c issues chunk c+2 into buf (c+1)%3
    for (int c = 0; c < 8; ++c) {
        if (c < 7) cp_wait<1>(); else cp_wait<0>();   // chunk c arrived
        __syncthreads();
        if (c + 2 <= 7) {
            uint32_t dst = sb + SM_B + (uint32_t)((c + 1) % 3) * 16384u;
            #pragma unroll
            for (int i = 0; i < 4; ++i) {
                int u = t + i * 256;
                cp_async16(dst + u * 16, &gWimg[(c + 2) * 16384 + u * 16]);
            }
            cp_commit();
        }

        const uint32_t bbase = sb + SM_B + (uint32_t)((c + 2) % 3) * 16384u;
        float acc[16];
        #pragma unroll
        for (int i = 0; i < 16; ++i) acc[i] = 0.f;

        // depth-1 pipelined B stream: flat iter i = kblk*2 + ng
        uint32_t bh[2][4];
        {
            uint32_t bad = bbase + (uint32_t)(nhalf * 4 + nbo) * 2048u + brow;
            LDSM_X4(bh[0], bad);
        }
        #pragma unroll
        for (int i = 0; i < 16; ++i) {
            const int cur = i & 1, nxt = cur ^ 1;
            if (i < 15) {
                int kn = i + 1;
                uint32_t bad = bbase
                    + (uint32_t)(nhalf * 4 + (kn & 1) * 2 + nbo) * 2048u
                    + (uint32_t)(kn >> 1) * 256u + brow;
                LDSM_X4(bh[nxt], bad);
            }
            const int kblk = i >> 1, go = (i & 1) * 8;
            mmaf16(acc + go + 0, af[kblk], bh[cur][0], bh[cur][1]);
            mmaf16(acc + go + 4, af[kblk], bh[cur][2], bh[cur][3]);
        }

        // ---- epilogue: permuted cols => 8 contiguous floats per thread per row ----
        float sc0 = attb[c * 64 + ns0];
        float sc1 = attb[c * 64 + ns1];
        float* o0 = ob0 + c * 64;
        float* o1 = ob1 + c * 64;
        float4 v00 = make_float4(fmaxf(acc[0]  * sc0, 0.f), fmaxf(acc[1]  * sc0, 0.f),
                                 fmaxf(acc[4]  * sc0, 0.f), fmaxf(acc[5]  * sc0, 0.f));
        float4 v01 = make_float4(fmaxf(acc[8]  * sc0, 0.f), fmaxf(acc[9]  * sc0, 0.f),
                                 fmaxf(acc[12] * sc0, 0.f), fmaxf(acc[13] * sc0, 0.f));
        float4 v10 = make_float4(fmaxf(acc[2]  * sc1, 0.f), fmaxf(acc[3]  * sc1, 0.f),
                                 fmaxf(acc[6]  * sc1, 0.f), fmaxf(acc[7]  * sc1, 0.f));
        float4 v11 = make_float4(fmaxf(acc[10] * sc1, 0.f), fmaxf(acc[11] * sc1, 0.f),
                                 fmaxf(acc[14] * sc1, 0.f), fmaxf(acc[15] * sc1, 0.f));
        *(float4*)(o0)     = v00;
        *(float4*)(o0 + 4) = v01;
        *(float4*)(o1)     = v10;
        *(float4*)(o1 + 4) = v11;
    }
}

// ---------------- launch ----------------
extern "C" void kernel_launch(void* const* d_in, const int* in_sizes, int n_in,
                              void* d_out, int out_size)
{
    const float* x    = (const float*)d_in[0];
    const float* Wlin = (const float*)d_in[1];
    const float* Watt = (const float*)d_in[2];
    const int*   mk   = (const int*)d_in[3];
    float*       out  = (float*)d_out;

    k_prep<<<96, 256>>>(Wlin, Watt);

    cudaFuncSetAttribute(agg_main, cudaFuncAttributeMaxDynamicSharedMemorySize, SMEM_BYTES);
    agg_main<<<BATCH, 256, SMEM_BYTES>>>(x, mk, out);
}

// round 12
// speedup vs baseline: 1.1516x; 1.1439x over previous
#include <cuda_runtime.h>
#include <cuda_fp16.h>
#include <cstdint>

#define BATCH 4096

// ---------------- device-global staging (written by pre-kernel) ----------------
// gWimg: fp16 B ldmatrix image, [chunk 8][nblk 8][kblk 8][tile 256B]
//   tile = 8 n-slots x 16 k fp16, slot nr at ((nr*32 + kh*16) ^ ((nr&4)?16:0)) + (k&7)*2
//   N-permutation: chunk=n>>6, cc=n&63, nhalf=cc>>5, w32=cc&31,
//     j=w32>>3, g=(w32>>1)&3, r=w32&1 ; nblk = nhalf*4 + g ; slot = 2j + r
__device__ __align__(1024) unsigned char gWimg[131072];
// gT[half][f][h] = sum_c Wlin[f][c] * Watt[(half*512 + c)*8 + h]  (L1-resident)
__device__ __align__(16) float gT[2][128][8];

// ---------------- PTX helpers ----------------
__device__ __forceinline__ uint32_t smem_u32(const void* p) {
    uint32_t a;
    asm("{ .reg .u64 t; cvta.to.shared.u64 t, %1; cvt.u32.u64 %0, t; }" : "=r"(a) : "l"(p));
    return a;
}
__device__ __forceinline__ void cp_async16(uint32_t saddr, const void* g) {
    asm volatile("cp.async.cg.shared.global [%0], [%1], 16;" :: "r"(saddr), "l"(g));
}
__device__ __forceinline__ void cp_commit() { asm volatile("cp.async.commit_group;"); }
template<int N> __device__ __forceinline__ void cp_wait() {
    asm volatile("cp.async.wait_group %0;" :: "n"(N));
}

#define LDSM_X4(d, a)                                                             \
    asm volatile("ldmatrix.sync.aligned.m8n8.x4.shared.b16 {%0,%1,%2,%3}, [%4];"  \
        : "=r"((d)[0]), "=r"((d)[1]), "=r"((d)[2]), "=r"((d)[3]) : "r"(a))

__device__ __forceinline__ void mmaf16(float* c, const uint32_t* a,
                                       uint32_t b0, uint32_t b1) {
    asm volatile("mma.sync.aligned.m16n8k16.row.col.f32.f16.f16.f32 "
        "{%0,%1,%2,%3}, {%4,%5,%6,%7}, {%8,%9}, {%0,%1,%2,%3};"
        : "+f"(c[0]), "+f"(c[1]), "+f"(c[2]), "+f"(c[3])
        : "r"(a[0]), "r"(a[1]), "r"(a[2]), "r"(a[3]), "r"(b0), "r"(b1));
}

__device__ __forceinline__ uint32_t pkh2(float a, float b) {
    __half2 t = __floats2half2_rn(a, b);
    return *reinterpret_cast<uint32_t*>(&t);
}

// ---------------- fused pre-kernel ----------------
__global__ void k_prep(const float* __restrict__ Wlin, const float* __restrict__ Watt) {
    int blk = blockIdx.x;
    if (blk < 32) {
        int t = blk * 256 + threadIdx.x;      // 0..8191
        int n = t & 511, ko = t >> 9;          // ko: 16 k-octs
        float v[8];
        #pragma unroll
        for (int j = 0; j < 8; ++j)
            v[j] = Wlin[(size_t)(ko * 8 + j) * 512 + n];
        int chunk = n >> 6, cc = n & 63, nhalf = cc >> 5, w32 = cc & 31;
        int jj = w32 >> 3, g = (w32 >> 1) & 3, r = w32 & 1;
        int nblk = chunk * 8 + nhalf * 4 + g;
        int nr = jj * 2 + r;
        int kblk = ko >> 1, kh = ko & 1;
        uint32_t off = (uint32_t)nblk * 2048u + (uint32_t)kblk * 256u
                     + (((uint32_t)nr * 32u + (uint32_t)kh * 16u) ^ ((nr & 4) ? 16u : 0u));
        *(uint4*)(&gWimg[off]) = make_uint4(pkh2(v[0], v[1]), pkh2(v[2], v[3]),
                                            pkh2(v[4], v[5]), pkh2(v[6], v[7]));
    } else {
        int t = (blk - 32) * 256 + threadIdx.x;   // 0..16383
        int o = t >> 3, sub = t & 7;               // 2048 outputs, 8 threads each
        int half = o >> 10, f = (o >> 3) & 127, h = o & 7;
        const float* wl = Wlin + (size_t)f * 512;
        const float* wa = Watt + (size_t)half * 512 * 8 + h;
        float acc = 0.f;
        int c0 = sub * 64;
        #pragma unroll 8
        for (int c = c0; c < c0 + 64; ++c)
            acc += wl[c] * wa[(size_t)c * 8];
        #pragma unroll
        for (int off = 4; off > 0; off >>= 1)
            acc += __shfl_xor_sync(0xffffffffu, acc, off);
        if (sub == 0) gT[half][f][h] = acc;
    }
}

// ---------------- main kernel: 256 threads, 1 batch, 2 CTAs/SM ----------------
// Warp tiling: mhalf(2) x nquad(4): m=32, n=16 per warp per chunk
// SMEM (bytes): A image [mblk4][kblk8][512B] @0 (16KB)
//               B ring 3 x 16KB @16384 (x fp32 stage aliased buf0+buf1)
//               SS[8] @65536 ; ATT[8][64] @65600  (total 67648)
#define SM_A     0
#define SM_B     16384
#define SM_SS    65536
#define SM_ATT   65600
#define SMEM_BYTES 67648

__global__ void __launch_bounds__(256, 2)
agg_main(const float* __restrict__ x, const int* __restrict__ mask,
         float* __restrict__ out)
{
    extern __shared__ unsigned char sm[];
    const int t = threadIdx.x, w = t >> 5, lane = t & 31;
    const int b = blockIdx.x;
    const uint32_t sb = smem_u32(sm);
    float* stage = (float*)(sm + SM_B);            // aliased on B buf0+buf1
    float* attb  = (float*)(sm + SM_ATT);
    float* sS    = (float*)(sm + SM_SS);
    const float* gT0 = &gT[0][0][0];
    const float* gT1 = &gT[1][0][0];

    // ---- G0: x (32KB) into stage ----
    const float* xp = x + (size_t)b * 8192;
    #pragma unroll
    for (int i = 0; i < 8; ++i) {
        int idx = t + i * 256;
        cp_async16(sb + SM_B + idx * 16, (const char*)xp + idx * 16);
    }
    cp_commit();
    // ---- G1: chunk 0 -> buf2 (free 16KB) ----
    #pragma unroll
    for (int i = 0; i < 4; ++i) {
        int u = t + i * 256;
        cp_async16(sb + SM_B + 32768u + u * 16, &gWimg[u * 16]);
    }
    cp_commit();
    cp_wait<1>();       // x arrived
    __syncthreads();

    // ---- convert x -> fp16 A tile image (1024 tasks of 8 elems) ----
    #pragma unroll
    for (int i = 0; i < 4; ++i) {
        int idx = t + i * 256;
        int m = idx >> 4, k0 = (idx & 15) * 8;      // m 0..63
        float4 v0 = *(float4*)(stage + m * 128 + k0);
        float4 v1 = *(float4*)(stage + m * 128 + k0 + 4);
        int mblk = m >> 4, rr = m & 15, kblk = k0 >> 4, kh = (k0 >> 3) & 1;
        uint32_t off = (uint32_t)mblk * 4096u + (uint32_t)kblk * 512u
                     + (((uint32_t)rr * 32u + (uint32_t)kh * 16u) ^ ((rr & 4) ? 16u : 0u));
        *(uint4*)(sm + SM_A + off) = make_uint4(pkh2(v0.x, v0.y), pkh2(v0.z, v0.w),
                                                pkh2(v1.x, v1.y), pkh2(v1.z, v1.w));
    }

    // ---- attention logits: 512 (r,h) tasks, x from stage (LDS broadcast) ----
    float dotv[2]; int rr2[2], hh2[2];
    #pragma unroll
    for (int j = 0; j < 2; ++j) {
        int idx2 = t + j * 256;
        int r = idx2 >> 3, h = idx2 & 7;
        const float* xr = stage + r * 128;
        float acc = 0.f;
        #pragma unroll 4
        for (int k = 0; k < 128; k += 4) {
            float4 xv = *(float4*)(xr + k);
            acc += xv.x * __ldg(gT1 + (k + 0) * 8 + h);
            acc += xv.y * __ldg(gT1 + (k + 1) * 8 + h);
            acc += xv.z * __ldg(gT1 + (k + 2) * 8 + h);
            acc += xv.w * __ldg(gT1 + (k + 3) * 8 + h);
        }
        dotv[j] = acc; rr2[j] = r; hh2[j] = h;
    }
    float srcv = 0.f;
    if (t < 8) {        // src term: row 0 vs T0, head = t
        const float* xr = stage;
        #pragma unroll 4
        for (int k = 0; k < 128; k += 4) {
            float4 xv = *(float4*)(xr + k);
            srcv += xv.x * __ldg(gT0 + (k + 0) * 8 + t);
            srcv += xv.y * __ldg(gT0 + (k + 1) * 8 + t);
            srcv += xv.z * __ldg(gT0 + (k + 2) * 8 + t);
            srcv += xv.w * __ldg(gT0 + (k + 3) * 8 + t);
        }
    }
    __syncthreads();    // stage fully read; A image visible
    if (t < 8) sS[t] = srcv;

    // ---- G2: chunk 1 -> buf0 (stage dead) ----
    #pragma unroll
    for (int i = 0; i < 4; ++i) {
        int u = t + i * 256;
        cp_async16(sb + SM_B + u * 16, &gWimg[16384 + u * 16]);
    }
    cp_commit();

    // ---- hoist A fragments (chunk-invariant): m=32 per warp -> 64 regs ----
    const int mhalf = w >> 2, q = w & 3;
    const int ja = lane >> 3, ra = lane & 7;
    const int ml  = (ja & 1) * 8 + ra, kha = ja >> 1;
    const uint32_t arow = (((uint32_t)ml * 32u + (uint32_t)kha * 16u) ^ ((ml & 4) ? 16u : 0u));
    uint32_t af[2][8][4];
    #pragma unroll
    for (int mb = 0; mb < 2; ++mb) {
        const uint32_t aad = sb + SM_A + (uint32_t)(mhalf * 2 + mb) * 4096u + arow;
        #pragma unroll
        for (int kblk = 0; kblk < 8; ++kblk)
            LDSM_X4(af[mb][kblk], aad + (uint32_t)kblk * 512u);
    }
    __syncthreads();    // sS visible

    // ---- logits -> attb ----
    #pragma unroll
    for (int j = 0; j < 2; ++j) {
        int n = rr2[j];
        float v = sS[hh2[j]] + dotv[j];
        v = (v >= 0.f) ? v : 0.2f * v;
        attb[hh2[j] * 64 + n] = v;
    }
    __syncthreads();

    // ---- softmax: warp w -> head w ----
    {
        int m0 = mask[b * 64 + lane];
        int m1 = mask[b * 64 + lane + 32];
        float v0 = attb[w * 64 + lane]      + (m0 == 0 ? -1e9f : 0.f);
        float v1 = attb[w * 64 + lane + 32] + (m1 == 0 ? -1e9f : 0.f);
        float mx = fmaxf(v0, v1);
        #pragma unroll
        for (int o = 16; o > 0; o >>= 1) mx = fmaxf(mx, __shfl_xor_sync(0xffffffffu, mx, o));
        float e0 = __expf(v0 - mx), e1 = __expf(v1 - mx);
        float sum = e0 + e1;
        #pragma unroll
        for (int o = 16; o > 0; o >>= 1) sum += __shfl_xor_sync(0xffffffffu, sum, o);
        float inv = 1.f / sum;
        attb[w * 64 + lane]      = e0 * inv;
        attb[w * 64 + lane + 32] = e1 * inv;
    }

    // ---- B addressing (warp q owns nblks {2q, 2q+1} per chunk) ----
    const int nbo = (ja >> 1), khb = ja & 1;
    const uint32_t brow = (((uint32_t)ra * 32u + (uint32_t)khb * 16u) ^ ((ra & 4) ? 16u : 0u));
    const uint32_t bwoff = (uint32_t)(q * 2 + nbo) * 2048u + brow;
    // epilogue: cols = (q>>1)*32 + 8*jc + 4*(q&1) + {0..3}; rows mhalf*32+er +{0,8,16,24}
    const int er = lane >> 2, jc = lane & 3;
    const int colb = (q >> 1) * 32 + jc * 8 + (q & 1) * 4;
    const int row0 = mhalf * 32 + er;
    float* obase = out + ((size_t)b * 64 + row0) * 512 + colb;

    // ---- mainloop: 8 chunks (chunk == head), 3-stage B ring, 1 sync/chunk ----
    for (int c = 0; c < 8; ++c) {
        if (c < 7) cp_wait<1>(); else cp_wait<0>();   // chunk c arrived
        __syncthreads();
        if (c + 2 <= 7) {
            uint32_t dst = sb + SM_B + (uint32_t)((c + 1) % 3) * 16384u;
            #pragma unroll
            for (int i = 0; i < 4; ++i) {
                int u = t + i * 256;
                cp_async16(dst + u * 16, &gWimg[(c + 2) * 16384 + u * 16]);
            }
            cp_commit();
        }

        const uint32_t bbase = sb + SM_B + (uint32_t)((c + 2) % 3) * 16384u + bwoff;
        float acc[16];
        #pragma unroll
        for (int i = 0; i < 16; ++i) acc[i] = 0.f;

        // depth-1 pipelined: 1 LDSM.x4 -> 4 MMAs per kblk
        uint32_t bh[2][4];
        LDSM_X4(bh[0], bbase);
        #pragma unroll
        for (int kblk = 0; kblk < 8; ++kblk) {
            const int cur = kblk & 1, nxt = cur ^ 1;
            if (kblk < 7)
                LDSM_X4(bh[nxt], bbase + (uint32_t)(kblk + 1) * 256u);
            mmaf16(acc + 0,  af[0][kblk], bh[cur][0], bh[cur][1]);
            mmaf16(acc + 4,  af[0][kblk], bh[cur][2], bh[cur][3]);
            mmaf16(acc + 8,  af[1][kblk], bh[cur][0], bh[cur][1]);
            mmaf16(acc + 12, af[1][kblk], bh[cur][2], bh[cur][3]);
        }

        // ---- epilogue: 4 rows x float4 (contiguous via permutation) ----
        float sc0 = attb[c * 64 + row0];
        float sc1 = attb[c * 64 + row0 + 8];
        float sc2 = attb[c * 64 + row0 + 16];
        float sc3 = attb[c * 64 + row0 + 24];
        float* o = obase + c * 64;
        float4 v0 = make_float4(fmaxf(acc[0]  * sc0, 0.f), fmaxf(acc[1]  * sc0, 0.f),
                                fmaxf(acc[4]  * sc0, 0.f), fmaxf(acc[5]  * sc0, 0.f));
        float4 v1 = make_float4(fmaxf(acc[2]  * sc1, 0.f), fmaxf(acc[3]  * sc1, 0.f),
                                fmaxf(acc[6]  * sc1, 0.f), fmaxf(acc[7]  * sc1, 0.f));
        float4 v2 = make_float4(fmaxf(acc[8]  * sc2, 0.f), fmaxf(acc[9]  * sc2, 0.f),
                                fmaxf(acc[12] * sc2, 0.f), fmaxf(acc[13] * sc2, 0.f));
        float4 v3 = make_float4(fmaxf(acc[10] * sc3, 0.f), fmaxf(acc[11] * sc3, 0.f),
                                fmaxf(acc[14] * sc3, 0.f), fmaxf(acc[15] * sc3, 0.f));
        *(float4*)(o)               = v0;
        *(float4*)(o + 8 * 512)     = v1;
        *(float4*)(o + 16 * 512)    = v2;
        *(float4*)(o + 24 * 512)    = v3;
    }
}

// ---------------- launch ----------------
extern "C" void kernel_launch(void* const* d_in, const int* in_sizes, int n_in,
                              void* d_out, int out_size)
{
    const float* x    = (const float*)d_in[0];
    const float* Wlin = (const float*)d_in[1];
    const float* Watt = (const float*)d_in[2];
    const int*   mk   = (const int*)d_in[3];
    float*       out  = (float*)d_out;

    k_prep<<<96, 256>>>(Wlin, Watt);

    cudaFuncSetAttribute(agg_main, cudaFuncAttributeMaxDynamicSharedMemorySize, SMEM_BYTES);
    agg_main<<<BATCH, 256, SMEM_BYTES>>>(x, mk, out);
}

// round 13
// speedup vs baseline: 1.3449x; 1.1678x over previous
#include <cuda_runtime.h>
#include <cuda_fp16.h>
#include <cstdint>

#define BATCH 4096

// ---------------- device-global staging (written by pre-kernel) ----------------
// gWimg: fp16 B ldmatrix image, [chunk 8][nblk 8][kblk 8][tile 256B]
//   tile = 8 n-slots x 16 k fp16, slot nr at ((nr*32 + kh*16) ^ ((nr&4)?16:0)) + (k&7)*2
//   N-permutation: chunk=n>>6, cc=n&63, nhalf=cc>>5, w32=cc&31,
//     j=w32>>3, g=(w32>>1)&3, r=w32&1 ; nblk = nhalf*4 + g ; slot = 2j + r
__device__ __align__(1024) unsigned char gWimg[131072];
// gT[half][f][h] = sum_c Wlin[f][c] * Watt[(half*512 + c)*8 + h]
__device__ __align__(16) float gT[2][128][8];

// ---------------- PTX helpers ----------------
__device__ __forceinline__ uint32_t smem_u32(const void* p) {
    uint32_t a;
    asm("{ .reg .u64 t; cvta.to.shared.u64 t, %1; cvt.u32.u64 %0, t; }" : "=r"(a) : "l"(p));
    return a;
}
__device__ __forceinline__ void cp_async16(uint32_t saddr, const void* g) {
    asm volatile("cp.async.cg.shared.global [%0], [%1], 16;" :: "r"(saddr), "l"(g));
}
__device__ __forceinline__ void cp_commit() { asm volatile("cp.async.commit_group;"); }
template<int N> __device__ __forceinline__ void cp_wait() {
    asm volatile("cp.async.wait_group %0;" :: "n"(N));
}

#define LDSM_X4(d, a)                                                             \
    asm volatile("ldmatrix.sync.aligned.m8n8.x4.shared.b16 {%0,%1,%2,%3}, [%4];"  \
        : "=r"((d)[0]), "=r"((d)[1]), "=r"((d)[2]), "=r"((d)[3]) : "r"(a))

__device__ __forceinline__ void mmaf16(float* c, const uint32_t* a,
                                       uint32_t b0, uint32_t b1) {
    asm volatile("mma.sync.aligned.m16n8k16.row.col.f32.f16.f16.f32 "
        "{%0,%1,%2,%3}, {%4,%5,%6,%7}, {%8,%9}, {%0,%1,%2,%3};"
        : "+f"(c[0]), "+f"(c[1]), "+f"(c[2]), "+f"(c[3])
        : "r"(a[0]), "r"(a[1]), "r"(a[2]), "r"(a[3]), "r"(b0), "r"(b1));
}

__device__ __forceinline__ uint32_t pkh2(float a, float b) {
    __half2 t = __floats2half2_rn(a, b);
    return *reinterpret_cast<uint32_t*>(&t);
}

// ---------------- fused pre-kernel ----------------
__global__ void k_prep(const float* __restrict__ Wlin, const float* __restrict__ Watt) {
    int blk = blockIdx.x;
    if (blk < 32) {
        int t = blk * 256 + threadIdx.x;      // 0..8191
        int n = t & 511, ko = t >> 9;          // ko: 16 k-octs
        float v[8];
        #pragma unroll
        for (int j = 0; j < 8; ++j)
            v[j] = Wlin[(size_t)(ko * 8 + j) * 512 + n];
        int chunk = n >> 6, cc = n & 63, nhalf = cc >> 5, w32 = cc & 31;
        int jj = w32 >> 3, g = (w32 >> 1) & 3, r = w32 & 1;
        int nblk = chunk * 8 + nhalf * 4 + g;
        int nr = jj * 2 + r;
        int kblk = ko >> 1, kh = ko & 1;
        uint32_t off = (uint32_t)nblk * 2048u + (uint32_t)kblk * 256u
                     + (((uint32_t)nr * 32u + (uint32_t)kh * 16u) ^ ((nr & 4) ? 16u : 0u));
        *(uint4*)(&gWimg[off]) = make_uint4(pkh2(v[0], v[1]), pkh2(v[2], v[3]),
                                            pkh2(v[4], v[5]), pkh2(v[6], v[7]));
    } else {
        int t = (blk - 32) * 256 + threadIdx.x;   // 0..16383
        int o = t >> 3, sub = t & 7;               // 2048 outputs, 8 threads each
        int half = o >> 10, f = (o >> 3) & 127, h = o & 7;
        const float* wl = Wlin + (size_t)f * 512;
        const float* wa = Watt + (size_t)half * 512 * 8 + h;
        float acc = 0.f;
        int c0 = sub * 64;
        #pragma unroll 8
        for (int c = c0; c < c0 + 64; ++c)
            acc += wl[c] * wa[(size_t)c * 8];
        #pragma unroll
        for (int off = 4; off > 0; off >>= 1)
            acc += __shfl_xor_sync(0xffffffffu, acc, off);
        if (sub == 0) gT[half][f][h] = acc;
    }
}

// ---------------- main kernel: 256 threads, 1 batch, 4 CTAs/SM ----------------
// Warp tiling (R9): mblk = w>>1 (m=16), nhalf = w&1 (n=32)
// SMEM (bytes): A image [mblk4][kblk8][512B] @0 (16KB)
//               B double buffer 2 x 16KB @16384 (x fp32 stage aliased on both)
//               T1 copy (4KB) @49152 ; SS[8] @53248 ; ATT[8][64] @53312
//               total 55360 -> 4 CTAs/SM (221.4KB of 228)
#define SM_A   0
#define SM_B   16384
#define SM_T1  49152
#define SM_SS  53248
#define SM_ATT 53312
#define SMEM_BYTES 55360

__global__ void __launch_bounds__(256, 4)
agg_main(const float* __restrict__ x, const int* __restrict__ mask,
         float* __restrict__ out)
{
    extern __shared__ unsigned char sm[];
    const int t = threadIdx.x, w = t >> 5, lane = t & 31;
    const int b = blockIdx.x;
    const uint32_t sb = smem_u32(sm);
    float* stage = (float*)(sm + SM_B);            // aliased on B buf0+buf1
    float* attb  = (float*)(sm + SM_ATT);
    float* sS    = (float*)(sm + SM_SS);
    const float* sT1 = (float*)(sm + SM_T1);
    const float* gT0 = &gT[0][0][0];

    // ---- G0: x (32KB) into stage + T1 (4KB) ----
    const float* xp = x + (size_t)b * 8192;
    #pragma unroll
    for (int i = 0; i < 8; ++i) {
        int idx = t + i * 256;
        cp_async16(sb + SM_B + idx * 16, (const char*)xp + idx * 16);
    }
    cp_async16(sb + SM_T1 + t * 16, (const char*)&gT[1][0][0] + t * 16);
    cp_commit();
    cp_wait<0>();
    __syncthreads();

    // ---- convert x -> fp16 A tile image (1024 tasks of 8 elems) ----
    #pragma unroll
    for (int i = 0; i < 4; ++i) {
        int idx = t + i * 256;
        int m = idx >> 4, k0 = (idx & 15) * 8;      // m 0..63
        float4 v0 = *(float4*)(stage + m * 128 + k0);
        float4 v1 = *(float4*)(stage + m * 128 + k0 + 4);
        int mblk = m >> 4, rr = m & 15, kblk = k0 >> 4, kh = (k0 >> 3) & 1;
        uint32_t off = (uint32_t)mblk * 4096u + (uint32_t)kblk * 512u
                     + (((uint32_t)rr * 32u + (uint32_t)kh * 16u) ^ ((rr & 4) ? 16u : 0u));
        *(uint4*)(sm + SM_A + off) = make_uint4(pkh2(v0.x, v0.y), pkh2(v0.z, v0.w),
                                                pkh2(v1.x, v1.y), pkh2(v1.z, v1.w));
    }

    // ---- attention logits: 512 (r,h) tasks, x from stage (LDS broadcast) ----
    float dotv[2]; int rr2[2], hh2[2];
    #pragma unroll
    for (int j = 0; j < 2; ++j) {
        int idx2 = t + j * 256;
        int r = idx2 >> 3, h = idx2 & 7;
        const float* xr = stage + r * 128;
        float acc = 0.f;
        #pragma unroll 4
        for (int k = 0; k < 128; k += 4) {
            float4 xv = *(float4*)(xr + k);
            acc += xv.x * sT1[(k + 0) * 8 + h];
            acc += xv.y * sT1[(k + 1) * 8 + h];
            acc += xv.z * sT1[(k + 2) * 8 + h];
            acc += xv.w * sT1[(k + 3) * 8 + h];
        }
        dotv[j] = acc; rr2[j] = r; hh2[j] = h;
    }
    float srcv = 0.f;
    if (t < 8) {        // src term: row 0 vs T0 (8 threads only -> __ldg)
        const float* xr = stage;
        #pragma unroll 4
        for (int k = 0; k < 128; k += 4) {
            float4 xv = *(float4*)(xr + k);
            srcv += xv.x * __ldg(gT0 + (k + 0) * 8 + t);
            srcv += xv.y * __ldg(gT0 + (k + 1) * 8 + t);
            srcv += xv.z * __ldg(gT0 + (k + 2) * 8 + t);
            srcv += xv.w * __ldg(gT0 + (k + 3) * 8 + t);
        }
    }
    __syncthreads();    // stage fully read; A image visible
    if (t < 8) sS[t] = srcv;

    // ---- chunk 0 -> buf0 (stage dead; loads overlap hoist/softmax) ----
    #pragma unroll
    for (int i = 0; i < 4; ++i) {
        int u = t + i * 256;
        cp_async16(sb + SM_B + u * 16, &gWimg[u * 16]);
    }
    cp_commit();

    // ---- hoist A fragments (chunk-invariant): 32 regs ----
    const int mblk = w >> 1, nhalf = w & 1;
    const int ja = lane >> 3, ra = lane & 7;
    const int ml  = (ja & 1) * 8 + ra, kha = ja >> 1;
    const uint32_t arow = (((uint32_t)ml * 32u + (uint32_t)kha * 16u) ^ ((ml & 4) ? 16u : 0u));
    const uint32_t aad0 = sb + SM_A + (uint32_t)mblk * 4096u + arow;
    uint32_t af[8][4];
    #pragma unroll
    for (int kblk = 0; kblk < 8; ++kblk)
        LDSM_X4(af[kblk], aad0 + (uint32_t)kblk * 512u);
    __syncthreads();    // sS visible

    // ---- logits -> attb ----
    #pragma unroll
    for (int j = 0; j < 2; ++j) {
        int n = rr2[j];
        float v = sS[hh2[j]] + dotv[j];
        v = (v >= 0.f) ? v : 0.2f * v;
        attb[hh2[j] * 64 + n] = v;
    }
    __syncthreads();

    // ---- softmax: warp w -> head w ----
    {
        int m0 = mask[b * 64 + lane];
        int m1 = mask[b * 64 + lane + 32];
        float v0 = attb[w * 64 + lane]      + (m0 == 0 ? -1e9f : 0.f);
        float v1 = attb[w * 64 + lane + 32] + (m1 == 0 ? -1e9f : 0.f);
        float mx = fmaxf(v0, v1);
        #pragma unroll
        for (int o = 16; o > 0; o >>= 1) mx = fmaxf(mx, __shfl_xor_sync(0xffffffffu, mx, o));
        float e0 = __expf(v0 - mx), e1 = __expf(v1 - mx);
        float sum = e0 + e1;
        #pragma unroll
        for (int o = 16; o > 0; o >>= 1) sum += __shfl_xor_sync(0xffffffffu, sum, o);
        float inv = 1.f / sum;
        attb[w * 64 + lane]      = e0 * inv;
        attb[w * 64 + lane + 32] = e1 * inv;
    }

    // ---- B addressing + epilogue lane mapping (permuted columns) ----
    const int nbo = (ja >> 1), khb = ja & 1;
    const uint32_t brow = (((uint32_t)ra * 32u + (uint32_t)khb * 16u) ^ ((ra & 4) ? 16u : 0u));
    const int er = lane >> 2, jc = lane & 3;
    const int ns0 = mblk * 16 + er;                 // ns1 = ns0 + 8
    float* ob0 = out + ((size_t)b * 64 + ns0) * 512 + nhalf * 32 + jc * 8;

    // ---- mainloop: 8 chunks (chunk == head), double-buffered B ----
    // chunk c in buf c&1; iter c issues chunk c+1 into buf (c+1)&1
    for (int c = 0; c < 8; ++c) {
        cp_wait<0>();          // chunk c arrived (its group committed last)
        __syncthreads();       // visibility + prior-chunk consumers done
        if (c < 7) {
            uint32_t dst = sb + SM_B + (uint32_t)((c + 1) & 1) * 16384u;
            #pragma unroll
            for (int i = 0; i < 4; ++i) {
                int u = t + i * 256;
                cp_async16(dst + u * 16, &gWimg[(c + 1) * 16384 + u * 16]);
            }
            cp_commit();
        }

        const uint32_t bbase = sb + SM_B + (uint32_t)(c & 1) * 16384u;
        float acc[16];
        #pragma unroll
        for (int i = 0; i < 16; ++i) acc[i] = 0.f;

        // depth-1 pipelined B stream: flat iter i = kblk*2 + ng
        uint32_t bh[2][4];
        {
            uint32_t bad = bbase + (uint32_t)(nhalf * 4 + nbo) * 2048u + brow;
            LDSM_X4(bh[0], bad);
        }
        #pragma unroll
        for (int i = 0; i < 16; ++i) {
            const int cur = i & 1, nxt = cur ^ 1;
            if (i < 15) {
                int kn = i + 1;
                uint32_t bad = bbase
                    + (uint32_t)(nhalf * 4 + (kn & 1) * 2 + nbo) * 2048u
                    + (uint32_t)(kn >> 1) * 256u + brow;
                LDSM_X4(bh[nxt], bad);
            }
            const int kblk = i >> 1, go = (i & 1) * 8;
            mmaf16(acc + go + 0, af[kblk], bh[cur][0], bh[cur][1]);
            mmaf16(acc + go + 4, af[kblk], bh[cur][2], bh[cur][3]);
        }

        // ---- epilogue: permuted cols => 8 contiguous floats per thread per row ----
        float sc0 = attb[c * 64 + ns0];
        float sc1 = attb[c * 64 + ns0 + 8];
        float* o0 = ob0 + c * 64;
        float4 v00 = make_float4(fmaxf(acc[0]  * sc0, 0.f), fmaxf(acc[1]  * sc0, 0.f),
                                 fmaxf(acc[4]  * sc0, 0.f), fmaxf(acc[5]  * sc0, 0.f));
        float4 v01 = make_float4(fmaxf(acc[8]  * sc0, 0.f), fmaxf(acc[9]  * sc0, 0.f),
                                 fmaxf(acc[12] * sc0, 0.f), fmaxf(acc[13] * sc0, 0.f));
        float4 v10 = make_float4(fmaxf(acc[2]  * sc1, 0.f), fmaxf(acc[3]  * sc1, 0.f),
                                 fmaxf(acc[6]  * sc1, 0.f), fmaxf(acc[7]  * sc1, 0.f));
        float4 v11 = make_float4(fmaxf(acc[10] * sc1, 0.f), fmaxf(acc[11] * sc1, 0.f),
                                 fmaxf(acc[14] * sc1, 0.f), fmaxf(acc[15] * sc1, 0.f));
        *(float4*)(o0)            = v00;
        *(float4*)(o0 + 4)        = v01;
        *(float4*)(o0 + 4096)     = v10;   // row ns0+8
        *(float4*)(o0 + 4096 + 4) = v11;
    }
}

// ---------------- launch ----------------
extern "C" void kernel_launch(void* const* d_in, const int* in_sizes, int n_in,
                              void* d_out, int out_size)
{
    const float* x    = (const float*)d_in[0];
    const float* Wlin = (const float*)d_in[1];
    const float* Watt = (const float*)d_in[2];
    const int*   mk   = (const int*)d_in[3];
    float*       out  = (float*)d_out;

    k_prep<<<96, 256>>>(Wlin, Watt);

    cudaFuncSetAttribute(agg_main, cudaFuncAttributeMaxDynamicSharedMemorySize, SMEM_BYTES);
    agg_main<<<BATCH, 256, SMEM_BYTES>>>(x, mk, out);
}